// round 8
// baseline (speedup 1.0000x reference)
#include <cuda_runtime.h>
#include <cstdint>
#include <cstddef>

#define VOCAB   32000
#define HID     768
#define HS1_N   128
#define TILE_M  128
#define NCHUNK  24          // 768 / 32
#define NTILES  512         // 65536 / 128

// ---------------- shared memory layout (bytes) ----------------
// Stage buf b: A at b*STAGE_PAIR, B at b*STAGE_PAIR + STAGE_BYTES
// Row stride 36 floats (32 data + 4 pad) -> conflict-free fragment LDS.
#define STAGE_BYTES 18432u              // 128 * 36 * 4
#define STAGE_PAIR  36864u
#define SM_B1       73728u              // 128 f32
#define SM_W2       74240u              // 128 f32
#define SM_PART     74752u              // 256 f32
#define SMEM_TOTAL  75776u
// Epilogue h-matrix reuses stage area: 128 * 132 * 4 = 67584 <= 73728.

static __device__ __forceinline__ void cp16(uint32_t dst, const void* src) {
    asm volatile("cp.async.cg.shared.global [%0], [%1], 16;" :: "r"(dst), "l"(src));
}

static __device__ __forceinline__ uint32_t smem_u32(const void* p) {
    uint32_t a;
    asm("{ .reg .u64 t; cvta.to.shared.u64 t, %1; cvt.u32.u64 %0, t; }" : "=r"(a) : "l"(p));
    return a;
}

static __device__ __forceinline__ void mma_tf32(float* d, const uint32_t* a,
                                                uint32_t b0, uint32_t b1) {
    asm volatile(
        "mma.sync.aligned.m16n8k8.row.col.f32.tf32.tf32.f32 "
        "{%0,%1,%2,%3}, {%4,%5,%6,%7}, {%8,%9}, {%0,%1,%2,%3};"
        : "+f"(d[0]), "+f"(d[1]), "+f"(d[2]), "+f"(d[3])
        : "r"(a[0]), "r"(a[1]), "r"(a[2]), "r"(a[3]), "r"(b0), "r"(b1));
}

// ---------------- device scratch (no dynamic alloc allowed) ----------------
__device__ float g_B[NCHUNK * 4096];   // W1h transposed [chunk][n(128)][k(32)], tf32-RN rounded
__device__ int   g_tk64;               // 1 if tk buffer is int64, 0 if int32

// ---------------- staging kernel ----------------
__global__ void stage_kernel(const float* __restrict__ W1, const int* __restrict__ tk32) {
    int idx = blockIdx.x * blockDim.x + threadIdx.x;
    if (idx < NCHUNK * 4096) {
        int c = idx >> 12;            // chunk
        int k = (idx >> 7) & 31;      // k within chunk
        int n = idx & 127;            // output col -> coalesced W1 read
        float v = W1[(size_t)(VOCAB + c * 32 + k) * HS1_N + n];
        float r;
        asm("cvt.rna.tf32.f32 %0, %1;" : "=f"(r) : "f"(v));   // RN to tf32 (unbiased)
        g_B[c * 4096 + n * 32 + k] = r;
    }
    if (idx == 0) {
        // int64 tk => odd 32-bit words all zero (tokens < 2^15)
        int z = 0;
        for (int i = 1; i < 32; i += 2) z |= tk32[i];
        g_tk64 = (z == 0) ? 1 : 0;
    }
}

// ---------------- main kernel ----------------
static __device__ __forceinline__ void load_stage(uint32_t sb, int buf, int c, int tid,
                                                  const float* __restrict__ atile) {
    uint32_t abase = sb + (uint32_t)buf * STAGE_PAIR;
    uint32_t bbase = abase + STAGE_BYTES;
    const float* bsrc = g_B + c * 4096;
#pragma unroll
    for (int q = 0; q < 4; q++) {
        int o = q * 256 + tid;        // 0..1023 float4 index
        int m = o >> 3, j = o & 7;    // row, 16B-group
        uint32_t doff = (uint32_t)(m * 36 + j * 4) * 4u;   // padded row stride
        cp16(abase + doff, atile + (size_t)m * HID + c * 32 + j * 4);
        cp16(bbase + doff, bsrc + o * 4);                  // g_B is linear per chunk
    }
    asm volatile("cp.async.commit_group;" ::: "memory");
}

__global__ __launch_bounds__(256, 2)
void classifier_kernel(const void* __restrict__ tk_raw,
                       const float* __restrict__ hs0,
                       const float* __restrict__ W1,
                       const float* __restrict__ b1,
                       const float* __restrict__ W2,
                       const float* __restrict__ b2,
                       float* __restrict__ out) {
    extern __shared__ char smem[];
    uint32_t sb = smem_u32(smem);
    int tid  = threadIdx.x;
    int warp = tid >> 5, lane = tid & 31;
    int lr = lane >> 2, lc = lane & 3;
    int wm = warp >> 1;               // 0..3  -> 32-row band
    int wn = warp & 1;                // 0..1  -> 64-col band
    int tile = blockIdx.x;

    if (tid < 128)  ((float*)(smem + SM_B1))[tid]       = b1[tid];
    else            ((float*)(smem + SM_W2))[tid - 128] = W2[tid - 128];

    const float* atile = hs0 + (size_t)tile * TILE_M * HID;

    float acc[2][8][4];
#pragma unroll
    for (int mt = 0; mt < 2; mt++)
#pragma unroll
        for (int nt = 0; nt < 8; nt++)
#pragma unroll
            for (int e = 0; e < 4; e++) acc[mt][nt][e] = 0.0f;

    // prologue
    load_stage(sb, 0, 0, tid, atile);

    for (int c = 0; c < NCHUNK; c++) {
        int buf = c & 1;
        if (c + 1 < NCHUNK) {
            load_stage(sb, (c + 1) & 1, c + 1, tid, atile);
            asm volatile("cp.async.wait_group 1;" ::: "memory");
        } else {
            asm volatile("cp.async.wait_group 0;" ::: "memory");
        }
        __syncthreads();

        const uint32_t* As = (const uint32_t*)(smem + buf * STAGE_PAIR);
        const uint32_t* Bs = (const uint32_t*)(smem + buf * STAGE_PAIR + STAGE_BYTES);

#pragma unroll
        for (int s = 0; s < 4; s++) {
            int k0 = s * 8 + lc;
            uint32_t a[2][4];
#pragma unroll
            for (int mt = 0; mt < 2; mt++) {
                int r = wm * 32 + mt * 16 + lr;
                a[mt][0] = As[r * 36 + k0];
                a[mt][1] = As[(r + 8) * 36 + k0];
                a[mt][2] = As[r * 36 + k0 + 4];
                a[mt][3] = As[(r + 8) * 36 + k0 + 4];
            }
#pragma unroll
            for (int nt = 0; nt < 8; nt++) {
                int n = wn * 64 + nt * 8 + lr;
                uint32_t b0 = Bs[n * 36 + k0];
                uint32_t b1f = Bs[n * 36 + k0 + 4];
                mma_tf32(acc[0][nt], a[0], b0, b1f);
                mma_tf32(acc[1][nt], a[1], b0, b1f);
            }
        }
        __syncthreads();   // protect buf before it is refilled next iteration
    }

    // ---------------- epilogue ----------------
    // Dump acc -> SMEM h matrix [128][132] (reuses stage area; all reads done).
    float* hs = (float*)smem;
#pragma unroll
    for (int mt = 0; mt < 2; mt++) {
#pragma unroll
        for (int nt = 0; nt < 8; nt++) {
            int r  = wm * 32 + mt * 16 + lr;
            int cc = wn * 64 + nt * 8 + lc * 2;
            *(float2*)&hs[r * 132 + cc]       = make_float2(acc[mt][nt][0], acc[mt][nt][1]);
            *(float2*)&hs[(r + 8) * 132 + cc] = make_float2(acc[mt][nt][2], acc[mt][nt][3]);
        }
    }
    __syncthreads();

    // Each pair of threads finishes one token: gather W1[tok] + b1, relu, dot W2.
    int row  = tid >> 1;
    int half = tid & 1;
    int gidx = tile * TILE_M + row;

    long long tok;
    if (g_tk64) tok = ((const long long*)tk_raw)[gidx];
    else        tok = (long long)((const int*)tk_raw)[gidx];

    const float4* trow = (const float4*)(W1 + (size_t)tok * HS1_N + half * 64);
    const float*  b1h  = ((const float*)(smem + SM_B1)) + half * 64;
    const float*  w2h  = ((const float*)(smem + SM_W2)) + half * 64;
    const float*  hrow = hs + row * 132 + half * 64;

    float sum = 0.0f;
#pragma unroll
    for (int jq = 0; jq < 16; jq++) {
        float4 t4 = trow[jq];
        const float* tv = &t4.x;
#pragma unroll
        for (int e = 0; e < 4; e++) {
            int j = jq * 4 + e;
            float v = hrow[j] + tv[e] + b1h[j];
            sum = fmaf(fmaxf(v, 0.0f), w2h[j], sum);
        }
    }
    ((float*)(smem + SM_PART))[tid] = sum;
    __syncthreads();

    if (tid < 128) {
        float o = ((float*)(smem + SM_PART))[2 * tid] +
                  ((float*)(smem + SM_PART))[2 * tid + 1] + b2[0];
        out[tile * TILE_M + tid] = o;
    }
}

// ---------------- launch ----------------
extern "C" void kernel_launch(void* const* d_in, const int* in_sizes, int n_in,
                              void* d_out, int out_size) {
    const void*  tk  = d_in[0];                   // int64 or int32 (auto-detected)
    const float* hs0 = (const float*)d_in[1];     // [16,4096,768]
    const float* W1  = (const float*)d_in[2];     // [32768,128]
    const float* b1  = (const float*)d_in[3];     // [128]
    const float* W2  = (const float*)d_in[4];     // [128]
    const float* b2  = (const float*)d_in[5];     // [1]
    float* out = (float*)d_out;                   // [65536]

    cudaFuncSetAttribute(classifier_kernel,
                         cudaFuncAttributeMaxDynamicSharedMemorySize, SMEM_TOTAL);

    stage_kernel<<<(NCHUNK * 4096 + 255) / 256, 256>>>(W1, (const int*)tk);
    classifier_kernel<<<NTILES, 256, SMEM_TOTAL>>>(tk, hs0, W1, b1, W2, b2, out);
}